// round 8
// baseline (speedup 1.0000x reference)
#include <cuda_runtime.h>
#include <math.h>

// 72 moments per batch, computed once by moments_kernel, consumed by gn_kernel.
#define BMAX 1024
__device__ float g_mom[BMAX * 72];

// ----------------------------------------------------------------------------
// Kernel A: per-batch sufficient-statistic reduction over N points.
// One block per batch. inv_cov staged through double-buffered shared memory
// with float4 loads: tile k+1 is prefetched into registers while tile k is
// reduced, so the LDG latency hides behind the ~60 FMA/point compute.
// Moments layout per batch (72 floats):
//   [0..5]   SW[pair]          = sum u * W_ab              (pair = sym(a,b))
//   [6..23]  SWs[pair*3+c]     = sum u * W_ab * s_c
//   [24..59] SWss[pair*6+mc]   = sum u * W_ab * (s s^T)_mc (mc = sym pair)
//   [60..62] SWt[a]            = sum u * (W trg)_a
//   [63..71] SWts[a*3+m]       = sum u * (W trg)_a * s_m
// with u = 2 * w^2.
// ----------------------------------------------------------------------------
__global__ __launch_bounds__(256) void moments_kernel(
    const float* __restrict__ src4, const float* __restrict__ trg4,
    const float* __restrict__ wgt, const float* __restrict__ invc, int N)
{
    const int TP = 256;                    // points per tile
    int b   = blockIdx.x;
    int tid = threadIdx.x;
    const float* sb = src4 + (size_t)b * 4 * N;
    const float* tb = trg4 + (size_t)b * 4 * N;
    const float* wb = wgt  + (size_t)b * N;
    const float* cb = invc + (size_t)b * N * 9;

    __shared__ float4 smc4[2][TP * 9 / 4];   // 2 x 9KB

    float acc[72];
#pragma unroll
    for (int i = 0; i < 72; i++) acc[i] = 0.f;

    int full_tiles = N / TP;

    float4 r0, r1, r2;
    // prefetch tile 0
    if (full_tiles > 0) {
        const float4* p = (const float4*)(cb);
        r0 = p[tid];
        r1 = p[tid + 256];
        if (tid < 64) r2 = p[tid + 512];
        smc4[0][tid] = r0;
        smc4[0][tid + 256] = r1;
        if (tid < 64) smc4[0][tid + 512] = r2;
    }
    __syncthreads();

    for (int tl = 0; tl < full_tiles; tl++) {
        // prefetch next tile into registers (overlaps with compute below)
        if (tl + 1 < full_tiles) {
            const float4* p = (const float4*)(cb + (size_t)(tl + 1) * TP * 9);
            r0 = p[tid];
            r1 = p[tid + 256];
            if (tid < 64) r2 = p[tid + 512];
        }

        int n = tl * TP + tid;
        {
            float sx = sb[n], sy = sb[N + n], sz = sb[2 * N + n];
            float tx = tb[n], ty = tb[N + n], tz = tb[2 * N + n];
            float w  = wb[n];
            float u  = 2.f * w * w;
            const float* c = (const float*)smc4[tl & 1] + tid * 9;
            float Wp[6];
            Wp[0] = u * c[0]; Wp[1] = u * c[1]; Wp[2] = u * c[2];
            Wp[3] = u * c[4]; Wp[4] = u * c[5]; Wp[5] = u * c[8];
            float sv[3] = {sx, sy, sz};
            float sp[6] = {sx * sx, sx * sy, sx * sz, sy * sy, sy * sz, sz * sz};

#pragma unroll
            for (int p = 0; p < 6; p++) acc[p] += Wp[p];
#pragma unroll
            for (int p = 0; p < 6; p++)
#pragma unroll
                for (int cc = 0; cc < 3; cc++) acc[6 + p * 3 + cc] += Wp[p] * sv[cc];
#pragma unroll
            for (int p = 0; p < 6; p++)
#pragma unroll
                for (int mc = 0; mc < 6; mc++) acc[24 + p * 6 + mc] += Wp[p] * sp[mc];

            float wt0 = Wp[0] * tx + Wp[1] * ty + Wp[2] * tz;
            float wt1 = Wp[1] * tx + Wp[3] * ty + Wp[4] * tz;
            float wt2 = Wp[2] * tx + Wp[4] * ty + Wp[5] * tz;
            acc[60] += wt0; acc[61] += wt1; acc[62] += wt2;
            float wt[3] = {wt0, wt1, wt2};
#pragma unroll
            for (int a = 0; a < 3; a++)
#pragma unroll
                for (int m2 = 0; m2 < 3; m2++) acc[63 + a * 3 + m2] += wt[a] * sv[m2];
        }

        if (tl + 1 < full_tiles) {
            __syncthreads();
            int nb = (tl + 1) & 1;
            smc4[nb][tid] = r0;
            smc4[nb][tid + 256] = r1;
            if (tid < 64) smc4[nb][tid + 512] = r2;
            __syncthreads();
        }
    }

    // tail (N not multiple of 256): direct scalar path
    for (int n = full_tiles * TP + tid; n < N; n += 256) {
        float sx = sb[n], sy = sb[N + n], sz = sb[2 * N + n];
        float tx = tb[n], ty = tb[N + n], tz = tb[2 * N + n];
        float w  = wb[n];
        float u  = 2.f * w * w;
        const float* c = cb + (size_t)n * 9;
        float Wp[6];
        Wp[0] = u * c[0]; Wp[1] = u * c[1]; Wp[2] = u * c[2];
        Wp[3] = u * c[4]; Wp[4] = u * c[5]; Wp[5] = u * c[8];
        float sv[3] = {sx, sy, sz};
        float sp[6] = {sx * sx, sx * sy, sx * sz, sy * sy, sy * sz, sz * sz};
#pragma unroll
        for (int p = 0; p < 6; p++) acc[p] += Wp[p];
#pragma unroll
        for (int p = 0; p < 6; p++)
#pragma unroll
            for (int cc = 0; cc < 3; cc++) acc[6 + p * 3 + cc] += Wp[p] * sv[cc];
#pragma unroll
        for (int p = 0; p < 6; p++)
#pragma unroll
            for (int mc = 0; mc < 6; mc++) acc[24 + p * 6 + mc] += Wp[p] * sp[mc];
        float wt0 = Wp[0] * tx + Wp[1] * ty + Wp[2] * tz;
        float wt1 = Wp[1] * tx + Wp[3] * ty + Wp[4] * tz;
        float wt2 = Wp[2] * tx + Wp[4] * ty + Wp[5] * tz;
        acc[60] += wt0; acc[61] += wt1; acc[62] += wt2;
        float wt[3] = {wt0, wt1, wt2};
#pragma unroll
        for (int a = 0; a < 3; a++)
#pragma unroll
            for (int m2 = 0; m2 < 3; m2++) acc[63 + a * 3 + m2] += wt[a] * sv[m2];
    }

    // warp reduce
#pragma unroll
    for (int i = 0; i < 72; i++) {
        float v = acc[i];
#pragma unroll
        for (int off = 16; off; off >>= 1) v += __shfl_down_sync(0xffffffffu, v, off);
        acc[i] = v;
    }
    __shared__ float red[8][72];
    int wid = tid >> 5, lane = tid & 31;
    __syncthreads();
    if (lane == 0) {
#pragma unroll
        for (int i = 0; i < 72; i++) red[wid][i] = acc[i];
    }
    __syncthreads();
    if (tid < 72) {
        float v = 0.f;
#pragma unroll
        for (int wdx = 0; wdx < 8; wdx++) v += red[wdx][tid];
        g_mom[b * 72 + tid] = v;
    }
}

// ----------------------------------------------------------------------------
// Kernel B helpers
// ----------------------------------------------------------------------------

// out = R^T * Wfull * R, W given as sym6 (00,01,02,11,12,22), out as sym6.
static __device__ __forceinline__ void congr(const float R[9], const float W[6], float o[6])
{
    float Y[9];
#pragma unroll
    for (int j = 0; j < 3; j++) {
        Y[0 + j] = W[0] * R[j] + W[1] * R[3 + j] + W[2] * R[6 + j];
        Y[3 + j] = W[1] * R[j] + W[3] * R[3 + j] + W[4] * R[6 + j];
        Y[6 + j] = W[2] * R[j] + W[4] * R[3 + j] + W[5] * R[6 + j];
    }
    int k = 0;
#pragma unroll
    for (int p = 0; p < 3; p++)
#pragma unroll
        for (int q = p; q < 3; q++)
            o[k++] = R[p] * Y[q] + R[3 + p] * Y[3 + q] + R[6 + p] * Y[6 + q];
}

// SE(3) exponential. |phi| stays < ~0.5 rad here, so MUFU sin/cos are
// accurate to ~1e-7 absolute — far inside the 1e-3 harness tolerance.
static __device__ __forceinline__ void se3exp(const float xi[6], float Re[9], float te[3])
{
    float r0 = xi[0], r1 = xi[1], r2 = xi[2];
    float p0 = xi[3], p1 = xi[4], p2 = xi[5];
    float th2 = p0 * p0 + p1 * p1 + p2 * p2;
    float A, Bc, Cc;
    if (th2 < 1e-12f) {
        A = 1.f; Bc = 0.5f; Cc = 1.f / 6.f;
    } else {
        float rth  = rsqrtf(th2);       // 1/theta
        float th   = th2 * rth;         // theta
        float sn   = __sinf(th), cs = __cosf(th);
        float ith2 = rth * rth;         // 1/theta^2
        A  = sn * rth;
        Bc = (1.f - cs) * ith2;
        Cc = (th - sn) * ith2 * rth;
    }
    float K[9]  = {0.f, -p2, p1, p2, 0.f, -p0, -p1, p0, 0.f};
    float pp[9] = {p0 * p0, p0 * p1, p0 * p2,
                   p1 * p0, p1 * p1, p1 * p2,
                   p2 * p0, p2 * p1, p2 * p2};
    float V[9];
#pragma unroll
    for (int i = 0; i < 9; i++) {
        float diag = (i == 0 || i == 4 || i == 8) ? 1.f : 0.f;
        float K2   = pp[i] - ((i == 0 || i == 4 || i == 8) ? th2 : 0.f);
        Re[i] = diag + A * K[i] + Bc * K2;
        V[i]  = diag + Bc * K[i] + Cc * K2;
    }
#pragma unroll
    for (int a = 0; a < 3; a++)
        te[a] = V[a * 3 + 0] * r0 + V[a * 3 + 1] * r1 + V[a * 3 + 2] * r2;
}

// ----------------------------------------------------------------------------
// Kernel B: Gauss-Newton, 1 thread/batch, ONE 256-thread block (2 warps/SMSP).
// Moments live in DYNAMIC SHARED MEMORY at stride 73 (9*tid mod 32 is
// conflict-free), freeing ~70 registers so ptxas can overlap the 10
// independent congruence chains per iteration.
// ----------------------------------------------------------------------------
__global__ __launch_bounds__(256) void gn_kernel(
    const float* __restrict__ Tinit, const float* __restrict__ Tsv,
    float* __restrict__ out, int B)
{
    extern __shared__ float smom[];   // 256 * 73 floats
    int tid = threadIdx.x;
    int b = blockIdx.x * 256 + tid;

    // cooperative coalesced fill of this block's moments
    {
        int bbase = blockIdx.x * 256;
        int nb = B - bbase; if (nb > 256) nb = 256;
        int tot = nb * 72;
        for (int i = tid; i < tot; i += 256) {
            int lb = i / 72, k = i % 72;
            smom[lb * 73 + k] = g_mom[(size_t)(bbase + lb) * 72 + k];
        }
        __syncthreads();
    }
    if (b >= B) return;

    const float* M = smom + tid * 73;
    // SW = M[0..5]; SWs = M[6+p*3+c]; SWss = M[24+p*6+mc];
    // SWt = M[60..62]; SWts = M[63+a*3+m]

    const float* Ti = Tinit + b * 16;
    float R[9], t[3];
    R[0] = Ti[0];  R[1] = Ti[1];  R[2] = Ti[2];  t[0] = Ti[3];
    R[3] = Ti[4];  R[4] = Ti[5];  R[5] = Ti[6];  t[1] = Ti[7];
    R[6] = Ti[8];  R[7] = Ti[9];  R[8] = Ti[10]; t[2] = Ti[11];

    const int IDX[3][3] = {{0, 1, 2}, {1, 3, 4}, {2, 4, 5}};

#pragma unroll
    for (int it = 0; it < 10; ++it) {
        // --- congruences P-type = R^T (moment slice) R ---
        float A6[6];
        {
            float Wm[6];
#pragma unroll
            for (int p = 0; p < 6; p++) Wm[p] = M[p];
            congr(R, Wm, A6);
        }
        float G[3][6];
#pragma unroll
        for (int mi = 0; mi < 3; mi++) {
            float Wm[6];
#pragma unroll
            for (int p = 0; p < 6; p++) Wm[p] = M[6 + p * 3 + mi];
            congr(R, Wm, G[mi]);
        }
        float E[6][6];
#pragma unroll
        for (int mc = 0; mc < 6; mc++) {
            float Wm[6];
#pragma unroll
            for (int p = 0; p < 6; p++) Wm[p] = M[24 + p * 6 + mc];
            congr(R, Wm, E[mc]);
        }

        // --- assemble H (6x6 symmetric) ---
        float H[36];
#pragma unroll
        for (int p = 0; p < 3; p++)
#pragma unroll
            for (int q = 0; q < 3; q++) H[p * 6 + q] = A6[IDX[p][q]];
#pragma unroll
        for (int p = 0; p < 3; p++) {
            float h0 = G[1][IDX[p][2]] - G[2][IDX[p][1]];
            float h1 = G[2][IDX[p][0]] - G[0][IDX[p][2]];
            float h2 = G[0][IDX[p][1]] - G[1][IDX[p][0]];
            H[p * 6 + 3] = h0; H[p * 6 + 4] = h1; H[p * 6 + 5] = h2;
            H[3 * 6 + p] = h0; H[4 * 6 + p] = h1; H[5 * 6 + p] = h2;
        }
        {
            const int jp[3]  = {2, 0, 1}, mp[3]  = {1, 2, 0};
            const int jm[3]  = {1, 2, 0}, mmn[3] = {2, 0, 1};
#pragma unroll
            for (int k = 0; k < 3; k++)
#pragma unroll
                for (int l = 0; l < 3; l++) {
                    float h = E[IDX[mp[k]][mp[l]]][IDX[jp[k]][jp[l]]]
                            - E[IDX[mp[k]][mmn[l]]][IDX[jp[k]][jm[l]]]
                            - E[IDX[mmn[k]][mp[l]]][IDX[jm[k]][jp[l]]]
                            + E[IDX[mmn[k]][mmn[l]]][IDX[jm[k]][jm[l]]];
                    H[(3 + k) * 6 + (3 + l)] = h;
                }
        }
#pragma unroll
        for (int d = 0; d < 6; d++) H[d * 6 + d] += 1e-8f;

        // --- g ---
        float v[3];
#pragma unroll
        for (int a = 0; a < 3; a++) {
            float acc2 = M[60 + a];
#pragma unroll
            for (int bb = 0; bb < 3; bb++) {
#pragma unroll
                for (int cc = 0; cc < 3; cc++)
                    acc2 -= R[bb * 3 + cc] * M[6 + IDX[a][bb] * 3 + cc];
                acc2 -= M[IDX[a][bb]] * t[bb];
            }
            v[a] = acc2;
        }
        float Ve[9];
#pragma unroll
        for (int a = 0; a < 3; a++)
#pragma unroll
            for (int mi = 0; mi < 3; mi++) {
                float acc2 = M[63 + a * 3 + mi];
#pragma unroll
                for (int bb = 0; bb < 3; bb++) {
#pragma unroll
                    for (int cc = 0; cc < 3; cc++)
                        acc2 -= R[bb * 3 + cc] * M[24 + IDX[a][bb] * 6 + IDX[cc][mi]];
                    acc2 -= t[bb] * M[6 + IDX[a][bb] * 3 + mi];
                }
                Ve[a * 3 + mi] = acc2;
            }
        float g[6];
#pragma unroll
        for (int p = 0; p < 3; p++)
            g[p] = -(R[p] * v[0] + R[3 + p] * v[1] + R[6 + p] * v[2]);
        float F[9];
#pragma unroll
        for (int j = 0; j < 3; j++)
#pragma unroll
            for (int mi = 0; mi < 3; mi++)
                F[j * 3 + mi] = R[j] * Ve[mi] + R[3 + j] * Ve[3 + mi] + R[6 + j] * Ve[6 + mi];
        g[3] = F[1 * 3 + 2] - F[2 * 3 + 1];
        g[4] = F[2 * 3 + 0] - F[0 * 3 + 2];
        g[5] = F[0 * 3 + 1] - F[1 * 3 + 0];

        // --- solve H dx = -g via Cholesky; rsqrt yields Lii and 1/Lii ---
        float Linv[6];
#pragma unroll
        for (int i = 0; i < 6; i++) {
#pragma unroll
            for (int j = 0; j < 6; j++) {
                if (j >= i) break;
                float s2 = H[i * 6 + j];
#pragma unroll
                for (int k2 = 0; k2 < 6; k2++) {
                    if (k2 >= j) break;
                    s2 -= H[i * 6 + k2] * H[j * 6 + k2];
                }
                H[i * 6 + j] = s2 * Linv[j];
            }
            float s2 = H[i * 6 + i];
#pragma unroll
            for (int k2 = 0; k2 < 6; k2++) {
                if (k2 >= i) break;
                s2 -= H[i * 6 + k2] * H[i * 6 + k2];
            }
            float rsq = rsqrtf(s2);
            H[i * 6 + i] = s2 * rsq;   // Lii
            Linv[i] = rsq;             // 1/Lii
        }
        float y[6];
#pragma unroll
        for (int i = 0; i < 6; i++) {
            float s2 = -g[i];
#pragma unroll
            for (int k2 = 0; k2 < 6; k2++) {
                if (k2 >= i) break;
                s2 -= H[i * 6 + k2] * y[k2];
            }
            y[i] = s2 * Linv[i];
        }
        float dx[6];
#pragma unroll
        for (int i = 5; i >= 0; i--) {
            float s2 = y[i];
#pragma unroll
            for (int k2 = 5; k2 > 0; k2--) {
                if (k2 <= i) break;
                s2 -= H[k2 * 6 + i] * dx[k2];
            }
            dx[i] = s2 * Linv[i];
        }

        // --- T <- T @ se3_exp(dx) ---
        float Re[9], te[3];
        se3exp(dx, Re, te);
        float Rn[9], tn[3];
#pragma unroll
        for (int r = 0; r < 3; r++) {
#pragma unroll
            for (int c = 0; c < 3; c++)
                Rn[r * 3 + c] = R[r * 3] * Re[c] + R[r * 3 + 1] * Re[3 + c] + R[r * 3 + 2] * Re[6 + c];
            tn[r] = R[r * 3] * te[0] + R[r * 3 + 1] * te[1] + R[r * 3 + 2] * te[2] + t[r];
        }
#pragma unroll
        for (int i = 0; i < 9; i++) R[i] = Rn[i];
#pragma unroll
        for (int i = 0; i < 3; i++) t[i] = tn[i];

        // warp-uniform early exit
        float mx = 0.f;
#pragma unroll
        for (int i = 0; i < 6; i++) mx = fmaxf(mx, fabsf(dx[i]));
        if (__all_sync(0xffffffffu, mx < 1e-4f)) break;
    }

    // --- out = inv(Tsv) @ T @ Tsv ---
    float Rs[9] = {Tsv[0], Tsv[1], Tsv[2], Tsv[4], Tsv[5], Tsv[6], Tsv[8], Tsv[9], Tsv[10]};
    float ts[3] = {Tsv[3], Tsv[7], Tsv[11]};
    float Rm[9], tm[3];
#pragma unroll
    for (int r = 0; r < 3; r++) {
#pragma unroll
        for (int c = 0; c < 3; c++)
            Rm[r * 3 + c] = R[r * 3] * Rs[c] + R[r * 3 + 1] * Rs[3 + c] + R[r * 3 + 2] * Rs[6 + c];
        tm[r] = R[r * 3] * ts[0] + R[r * 3 + 1] * ts[1] + R[r * 3 + 2] * ts[2] + t[r] - ts[r];
    }
    float* o = out + b * 16;
#pragma unroll
    for (int i = 0; i < 3; i++) {
#pragma unroll
        for (int j = 0; j < 3; j++)
            o[i * 4 + j] = Rs[i] * Rm[j] + Rs[3 + i] * Rm[3 + j] + Rs[6 + i] * Rm[6 + j];
        o[i * 4 + 3] = Rs[i] * tm[0] + Rs[3 + i] * tm[1] + Rs[6 + i] * tm[2];
    }
    o[12] = 0.f; o[13] = 0.f; o[14] = 0.f; o[15] = 1.f;
}

// ----------------------------------------------------------------------------
extern "C" void kernel_launch(void* const* d_in, const int* in_sizes, int n_in,
                              void* d_out, int out_size)
{
    const float* src4  = (const float*)d_in[0];  // (B,4,N)
    const float* trg4  = (const float*)d_in[1];  // (B,4,N)
    const float* wgt   = (const float*)d_in[2];  // (B,1,N)
    const float* Tinit = (const float*)d_in[3];  // (B,4,4)
    const float* invc  = (const float*)d_in[4];  // (B,N,3,3)
    const float* Tsv   = (const float*)d_in[5];  // (4,4)
    float* out = (float*)d_out;                  // (B,4,4)

    int B = in_sizes[3] / 16;
    int N = in_sizes[2] / B;

    int gn_smem = 256 * 73 * sizeof(float);   // 74752 B
    cudaFuncSetAttribute(gn_kernel, cudaFuncAttributeMaxDynamicSharedMemorySize, gn_smem);

    moments_kernel<<<B, 256>>>(src4, trg4, wgt, invc, N);
    gn_kernel<<<(B + 255) / 256, 256, gn_smem>>>(Tinit, Tsv, out, B);
}

// round 9
// speedup vs baseline: 1.0920x; 1.0920x over previous
#include <cuda_runtime.h>
#include <math.h>

// 72 moments per batch, computed once by moments_kernel, consumed by gn_kernel.
#define BMAX 1024
__device__ float g_mom[BMAX * 72];

// ----------------------------------------------------------------------------
// Kernel A: per-batch sufficient-statistic reduction over N points.
// One block per batch. inv_cov staged through double-buffered shared memory
// with float4 loads: tile k+1 is prefetched into registers while tile k is
// reduced, so the LDG latency hides behind the ~60 FMA/point compute.
// (Measured ~4.9us in R8 — keep unchanged.)
// Moments layout per batch (72 floats):
//   [0..5]   SW[pair]          = sum u * W_ab              (pair = sym(a,b))
//   [6..23]  SWs[pair*3+c]     = sum u * W_ab * s_c
//   [24..59] SWss[pair*6+mc]   = sum u * W_ab * (s s^T)_mc (mc = sym pair)
//   [60..62] SWt[a]            = sum u * (W trg)_a
//   [63..71] SWts[a*3+m]       = sum u * (W trg)_a * s_m
// with u = 2 * w^2.
// ----------------------------------------------------------------------------
__global__ __launch_bounds__(256) void moments_kernel(
    const float* __restrict__ src4, const float* __restrict__ trg4,
    const float* __restrict__ wgt, const float* __restrict__ invc, int N)
{
    const int TP = 256;                    // points per tile
    int b   = blockIdx.x;
    int tid = threadIdx.x;
    const float* sb = src4 + (size_t)b * 4 * N;
    const float* tb = trg4 + (size_t)b * 4 * N;
    const float* wb = wgt  + (size_t)b * N;
    const float* cb = invc + (size_t)b * N * 9;

    __shared__ float4 smc4[2][TP * 9 / 4];   // 2 x 9KB

    float acc[72];
#pragma unroll
    for (int i = 0; i < 72; i++) acc[i] = 0.f;

    int full_tiles = N / TP;

    float4 r0, r1, r2;
    // prefetch tile 0
    if (full_tiles > 0) {
        const float4* p = (const float4*)(cb);
        r0 = p[tid];
        r1 = p[tid + 256];
        if (tid < 64) r2 = p[tid + 512];
        smc4[0][tid] = r0;
        smc4[0][tid + 256] = r1;
        if (tid < 64) smc4[0][tid + 512] = r2;
    }
    __syncthreads();

    for (int tl = 0; tl < full_tiles; tl++) {
        // prefetch next tile into registers (overlaps with compute below)
        if (tl + 1 < full_tiles) {
            const float4* p = (const float4*)(cb + (size_t)(tl + 1) * TP * 9);
            r0 = p[tid];
            r1 = p[tid + 256];
            if (tid < 64) r2 = p[tid + 512];
        }

        int n = tl * TP + tid;
        {
            float sx = sb[n], sy = sb[N + n], sz = sb[2 * N + n];
            float tx = tb[n], ty = tb[N + n], tz = tb[2 * N + n];
            float w  = wb[n];
            float u  = 2.f * w * w;
            const float* c = (const float*)smc4[tl & 1] + tid * 9;
            float Wp[6];
            Wp[0] = u * c[0]; Wp[1] = u * c[1]; Wp[2] = u * c[2];
            Wp[3] = u * c[4]; Wp[4] = u * c[5]; Wp[5] = u * c[8];
            float sv[3] = {sx, sy, sz};
            float sp[6] = {sx * sx, sx * sy, sx * sz, sy * sy, sy * sz, sz * sz};

#pragma unroll
            for (int p = 0; p < 6; p++) acc[p] += Wp[p];
#pragma unroll
            for (int p = 0; p < 6; p++)
#pragma unroll
                for (int cc = 0; cc < 3; cc++) acc[6 + p * 3 + cc] += Wp[p] * sv[cc];
#pragma unroll
            for (int p = 0; p < 6; p++)
#pragma unroll
                for (int mc = 0; mc < 6; mc++) acc[24 + p * 6 + mc] += Wp[p] * sp[mc];

            float wt0 = Wp[0] * tx + Wp[1] * ty + Wp[2] * tz;
            float wt1 = Wp[1] * tx + Wp[3] * ty + Wp[4] * tz;
            float wt2 = Wp[2] * tx + Wp[4] * ty + Wp[5] * tz;
            acc[60] += wt0; acc[61] += wt1; acc[62] += wt2;
            float wt[3] = {wt0, wt1, wt2};
#pragma unroll
            for (int a = 0; a < 3; a++)
#pragma unroll
                for (int m2 = 0; m2 < 3; m2++) acc[63 + a * 3 + m2] += wt[a] * sv[m2];
        }

        if (tl + 1 < full_tiles) {
            __syncthreads();
            int nb = (tl + 1) & 1;
            smc4[nb][tid] = r0;
            smc4[nb][tid + 256] = r1;
            if (tid < 64) smc4[nb][tid + 512] = r2;
            __syncthreads();
        }
    }

    // tail (N not multiple of 256): direct scalar path
    for (int n = full_tiles * TP + tid; n < N; n += 256) {
        float sx = sb[n], sy = sb[N + n], sz = sb[2 * N + n];
        float tx = tb[n], ty = tb[N + n], tz = tb[2 * N + n];
        float w  = wb[n];
        float u  = 2.f * w * w;
        const float* c = cb + (size_t)n * 9;
        float Wp[6];
        Wp[0] = u * c[0]; Wp[1] = u * c[1]; Wp[2] = u * c[2];
        Wp[3] = u * c[4]; Wp[4] = u * c[5]; Wp[5] = u * c[8];
        float sv[3] = {sx, sy, sz};
        float sp[6] = {sx * sx, sx * sy, sx * sz, sy * sy, sy * sz, sz * sz};
#pragma unroll
        for (int p = 0; p < 6; p++) acc[p] += Wp[p];
#pragma unroll
        for (int p = 0; p < 6; p++)
#pragma unroll
            for (int cc = 0; cc < 3; cc++) acc[6 + p * 3 + cc] += Wp[p] * sv[cc];
#pragma unroll
        for (int p = 0; p < 6; p++)
#pragma unroll
            for (int mc = 0; mc < 6; mc++) acc[24 + p * 6 + mc] += Wp[p] * sp[mc];
        float wt0 = Wp[0] * tx + Wp[1] * ty + Wp[2] * tz;
        float wt1 = Wp[1] * tx + Wp[3] * ty + Wp[4] * tz;
        float wt2 = Wp[2] * tx + Wp[4] * ty + Wp[5] * tz;
        acc[60] += wt0; acc[61] += wt1; acc[62] += wt2;
        float wt[3] = {wt0, wt1, wt2};
#pragma unroll
        for (int a = 0; a < 3; a++)
#pragma unroll
            for (int m2 = 0; m2 < 3; m2++) acc[63 + a * 3 + m2] += wt[a] * sv[m2];
    }

    // warp reduce
#pragma unroll
    for (int i = 0; i < 72; i++) {
        float v = acc[i];
#pragma unroll
        for (int off = 16; off; off >>= 1) v += __shfl_down_sync(0xffffffffu, v, off);
        acc[i] = v;
    }
    __shared__ float red[8][72];
    int wid = tid >> 5, lane = tid & 31;
    __syncthreads();
    if (lane == 0) {
#pragma unroll
        for (int i = 0; i < 72; i++) red[wid][i] = acc[i];
    }
    __syncthreads();
    if (tid < 72) {
        float v = 0.f;
#pragma unroll
        for (int wdx = 0; wdx < 8; wdx++) v += red[wdx][tid];
        g_mom[b * 72 + tid] = v;
    }
}

// ----------------------------------------------------------------------------
// Kernel B helpers
// ----------------------------------------------------------------------------

// out = R^T * Wfull * R, W given as sym6 (00,01,02,11,12,22), out as sym6.
static __device__ __forceinline__ void congr(const float R[9], const float W[6], float o[6])
{
    float Y[9];
#pragma unroll
    for (int j = 0; j < 3; j++) {
        Y[0 + j] = W[0] * R[j] + W[1] * R[3 + j] + W[2] * R[6 + j];
        Y[3 + j] = W[1] * R[j] + W[3] * R[3 + j] + W[4] * R[6 + j];
        Y[6 + j] = W[2] * R[j] + W[4] * R[3 + j] + W[5] * R[6 + j];
    }
    int k = 0;
#pragma unroll
    for (int p = 0; p < 3; p++)
#pragma unroll
        for (int q = p; q < 3; q++)
            o[k++] = R[p] * Y[q] + R[3 + p] * Y[3 + q] + R[6 + p] * Y[6 + q];
}

// SE(3) exponential. |phi| stays < ~0.5 rad here, so MUFU sin/cos are
// accurate to ~1e-7 absolute — far inside the 1e-3 harness tolerance.
static __device__ __forceinline__ void se3exp(const float xi[6], float Re[9], float te[3])
{
    float r0 = xi[0], r1 = xi[1], r2 = xi[2];
    float p0 = xi[3], p1 = xi[4], p2 = xi[5];
    float th2 = p0 * p0 + p1 * p1 + p2 * p2;
    float A, Bc, Cc;
    if (th2 < 1e-12f) {
        A = 1.f; Bc = 0.5f; Cc = 1.f / 6.f;
    } else {
        float rth  = rsqrtf(th2);       // 1/theta
        float th   = th2 * rth;         // theta
        float sn   = __sinf(th), cs = __cosf(th);
        float ith2 = rth * rth;         // 1/theta^2
        A  = sn * rth;
        Bc = (1.f - cs) * ith2;
        Cc = (th - sn) * ith2 * rth;
    }
    float K[9]  = {0.f, -p2, p1, p2, 0.f, -p0, -p1, p0, 0.f};
    float pp[9] = {p0 * p0, p0 * p1, p0 * p2,
                   p1 * p0, p1 * p1, p1 * p2,
                   p2 * p0, p2 * p1, p2 * p2};
    float V[9];
#pragma unroll
    for (int i = 0; i < 9; i++) {
        float diag = (i == 0 || i == 4 || i == 8) ? 1.f : 0.f;
        float K2   = pp[i] - ((i == 0 || i == 4 || i == 8) ? th2 : 0.f);
        Re[i] = diag + A * K[i] + Bc * K2;
        V[i]  = diag + Bc * K[i] + Cc * K2;
    }
#pragma unroll
    for (int a = 0; a < 3; a++)
        te[a] = V[a * 3 + 0] * r0 + V[a * 3 + 1] * r1 + V[a * 3 + 2] * r2;
}

// ----------------------------------------------------------------------------
// Kernel B: Gauss-Newton, 1 thread/batch, ONE 256-thread block (2 warps/SMSP),
// moments in REGISTERS (R7 configuration — measured 15.1us). Straight-line
// unrolled loop with warp-uniform early exit.
// ----------------------------------------------------------------------------
__global__ __launch_bounds__(256) void gn_kernel(
    const float* __restrict__ Tinit, const float* __restrict__ Tsv,
    float* __restrict__ out, int B)
{
    int b = blockIdx.x * 256 + threadIdx.x;
    if (b >= B) return;

    float m[72];
#pragma unroll
    for (int i = 0; i < 72; i++) m[i] = g_mom[b * 72 + i];
    const float* SW   = m;         // 6
    const float* SWs  = m + 6;     // [pair*3 + c]
    const float* SWss = m + 24;    // [pair*6 + mc]
    const float* SWt  = m + 60;    // 3
    const float* SWts = m + 63;    // [a*3 + m]

    const float* Ti = Tinit + b * 16;
    float R[9], t[3];
    R[0] = Ti[0];  R[1] = Ti[1];  R[2] = Ti[2];  t[0] = Ti[3];
    R[3] = Ti[4];  R[4] = Ti[5];  R[5] = Ti[6];  t[1] = Ti[7];
    R[6] = Ti[8];  R[7] = Ti[9];  R[8] = Ti[10]; t[2] = Ti[11];

    const int IDX[3][3] = {{0, 1, 2}, {1, 3, 4}, {2, 4, 5}};

#pragma unroll
    for (int it = 0; it < 10; ++it) {
        // --- congruences P-type = R^T (moment slice) R ---
        float A6[6];
        congr(R, SW, A6);
        float G[3][6];
#pragma unroll
        for (int mi = 0; mi < 3; mi++) {
            float Wm[6];
#pragma unroll
            for (int p = 0; p < 6; p++) Wm[p] = SWs[p * 3 + mi];
            congr(R, Wm, G[mi]);
        }
        float E[6][6];
#pragma unroll
        for (int mc = 0; mc < 6; mc++) {
            float Wm[6];
#pragma unroll
            for (int p = 0; p < 6; p++) Wm[p] = SWss[p * 6 + mc];
            congr(R, Wm, E[mc]);
        }

        // --- assemble H (6x6 symmetric) ---
        float H[36];
#pragma unroll
        for (int p = 0; p < 3; p++)
#pragma unroll
            for (int q = 0; q < 3; q++) H[p * 6 + q] = A6[IDX[p][q]];
#pragma unroll
        for (int p = 0; p < 3; p++) {
            float h0 = G[1][IDX[p][2]] - G[2][IDX[p][1]];
            float h1 = G[2][IDX[p][0]] - G[0][IDX[p][2]];
            float h2 = G[0][IDX[p][1]] - G[1][IDX[p][0]];
            H[p * 6 + 3] = h0; H[p * 6 + 4] = h1; H[p * 6 + 5] = h2;
            H[3 * 6 + p] = h0; H[4 * 6 + p] = h1; H[5 * 6 + p] = h2;
        }
        {
            const int jp[3]  = {2, 0, 1}, mp[3]  = {1, 2, 0};
            const int jm[3]  = {1, 2, 0}, mmn[3] = {2, 0, 1};
#pragma unroll
            for (int k = 0; k < 3; k++)
#pragma unroll
                for (int l = 0; l < 3; l++) {
                    float h = E[IDX[mp[k]][mp[l]]][IDX[jp[k]][jp[l]]]
                            - E[IDX[mp[k]][mmn[l]]][IDX[jp[k]][jm[l]]]
                            - E[IDX[mmn[k]][mp[l]]][IDX[jm[k]][jp[l]]]
                            + E[IDX[mmn[k]][mmn[l]]][IDX[jm[k]][jm[l]]];
                    H[(3 + k) * 6 + (3 + l)] = h;
                }
        }
#pragma unroll
        for (int d = 0; d < 6; d++) H[d * 6 + d] += 1e-8f;

        // --- g ---
        float v[3];
#pragma unroll
        for (int a = 0; a < 3; a++) {
            float acc2 = SWt[a];
#pragma unroll
            for (int bb = 0; bb < 3; bb++) {
#pragma unroll
                for (int cc = 0; cc < 3; cc++)
                    acc2 -= R[bb * 3 + cc] * SWs[IDX[a][bb] * 3 + cc];
                acc2 -= SW[IDX[a][bb]] * t[bb];
            }
            v[a] = acc2;
        }
        float Ve[9];
#pragma unroll
        for (int a = 0; a < 3; a++)
#pragma unroll
            for (int mi = 0; mi < 3; mi++) {
                float acc2 = SWts[a * 3 + mi];
#pragma unroll
                for (int bb = 0; bb < 3; bb++) {
#pragma unroll
                    for (int cc = 0; cc < 3; cc++)
                        acc2 -= R[bb * 3 + cc] * SWss[IDX[a][bb] * 6 + IDX[cc][mi]];
                    acc2 -= t[bb] * SWs[IDX[a][bb] * 3 + mi];
                }
                Ve[a * 3 + mi] = acc2;
            }
        float g[6];
#pragma unroll
        for (int p = 0; p < 3; p++)
            g[p] = -(R[p] * v[0] + R[3 + p] * v[1] + R[6 + p] * v[2]);
        float F[9];
#pragma unroll
        for (int j = 0; j < 3; j++)
#pragma unroll
            for (int mi = 0; mi < 3; mi++)
                F[j * 3 + mi] = R[j] * Ve[mi] + R[3 + j] * Ve[3 + mi] + R[6 + j] * Ve[6 + mi];
        g[3] = F[1 * 3 + 2] - F[2 * 3 + 1];
        g[4] = F[2 * 3 + 0] - F[0 * 3 + 2];
        g[5] = F[0 * 3 + 1] - F[1 * 3 + 0];

        // --- solve H dx = -g via Cholesky; rsqrt yields Lii and 1/Lii ---
        float Linv[6];
#pragma unroll
        for (int i = 0; i < 6; i++) {
#pragma unroll
            for (int j = 0; j < 6; j++) {
                if (j >= i) break;
                float s2 = H[i * 6 + j];
#pragma unroll
                for (int k2 = 0; k2 < 6; k2++) {
                    if (k2 >= j) break;
                    s2 -= H[i * 6 + k2] * H[j * 6 + k2];
                }
                H[i * 6 + j] = s2 * Linv[j];
            }
            float s2 = H[i * 6 + i];
#pragma unroll
            for (int k2 = 0; k2 < 6; k2++) {
                if (k2 >= i) break;
                s2 -= H[i * 6 + k2] * H[i * 6 + k2];
            }
            float rsq = rsqrtf(s2);
            H[i * 6 + i] = s2 * rsq;   // Lii
            Linv[i] = rsq;             // 1/Lii
        }
        float y[6];
#pragma unroll
        for (int i = 0; i < 6; i++) {
            float s2 = -g[i];
#pragma unroll
            for (int k2 = 0; k2 < 6; k2++) {
                if (k2 >= i) break;
                s2 -= H[i * 6 + k2] * y[k2];
            }
            y[i] = s2 * Linv[i];
        }
        float dx[6];
#pragma unroll
        for (int i = 5; i >= 0; i--) {
            float s2 = y[i];
#pragma unroll
            for (int k2 = 5; k2 > 0; k2--) {
                if (k2 <= i) break;
                s2 -= H[k2 * 6 + i] * dx[k2];
            }
            dx[i] = s2 * Linv[i];
        }

        // --- T <- T @ se3_exp(dx) ---
        float Re[9], te[3];
        se3exp(dx, Re, te);
        float Rn[9], tn[3];
#pragma unroll
        for (int r = 0; r < 3; r++) {
#pragma unroll
            for (int c = 0; c < 3; c++)
                Rn[r * 3 + c] = R[r * 3] * Re[c] + R[r * 3 + 1] * Re[3 + c] + R[r * 3 + 2] * Re[6 + c];
            tn[r] = R[r * 3] * te[0] + R[r * 3 + 1] * te[1] + R[r * 3 + 2] * te[2] + t[r];
        }
#pragma unroll
        for (int i = 0; i < 9; i++) R[i] = Rn[i];
#pragma unroll
        for (int i = 0; i < 3; i++) t[i] = tn[i];

        // warp-uniform early exit
        float mx = 0.f;
#pragma unroll
        for (int i = 0; i < 6; i++) mx = fmaxf(mx, fabsf(dx[i]));
        if (__all_sync(0xffffffffu, mx < 1e-4f)) break;
    }

    // --- out = inv(Tsv) @ T @ Tsv ---
    float Rs[9] = {Tsv[0], Tsv[1], Tsv[2], Tsv[4], Tsv[5], Tsv[6], Tsv[8], Tsv[9], Tsv[10]};
    float ts[3] = {Tsv[3], Tsv[7], Tsv[11]};
    float Rm[9], tm[3];
#pragma unroll
    for (int r = 0; r < 3; r++) {
#pragma unroll
        for (int c = 0; c < 3; c++)
            Rm[r * 3 + c] = R[r * 3] * Rs[c] + R[r * 3 + 1] * Rs[3 + c] + R[r * 3 + 2] * Rs[6 + c];
        tm[r] = R[r * 3] * ts[0] + R[r * 3 + 1] * ts[1] + R[r * 3 + 2] * ts[2] + t[r] - ts[r];
    }
    float* o = out + b * 16;
#pragma unroll
    for (int i = 0; i < 3; i++) {
#pragma unroll
        for (int j = 0; j < 3; j++)
            o[i * 4 + j] = Rs[i] * Rm[j] + Rs[3 + i] * Rm[3 + j] + Rs[6 + i] * Rm[6 + j];
        o[i * 4 + 3] = Rs[i] * tm[0] + Rs[3 + i] * tm[1] + Rs[6 + i] * tm[2];
    }
    o[12] = 0.f; o[13] = 0.f; o[14] = 0.f; o[15] = 1.f;
}

// ----------------------------------------------------------------------------
extern "C" void kernel_launch(void* const* d_in, const int* in_sizes, int n_in,
                              void* d_out, int out_size)
{
    const float* src4  = (const float*)d_in[0];  // (B,4,N)
    const float* trg4  = (const float*)d_in[1];  // (B,4,N)
    const float* wgt   = (const float*)d_in[2];  // (B,1,N)
    const float* Tinit = (const float*)d_in[3];  // (B,4,4)
    const float* invc  = (const float*)d_in[4];  // (B,N,3,3)
    const float* Tsv   = (const float*)d_in[5];  // (4,4)
    float* out = (float*)d_out;                  // (B,4,4)

    int B = in_sizes[3] / 16;
    int N = in_sizes[2] / B;

    moments_kernel<<<B, 256>>>(src4, trg4, wgt, invc, N);
    gn_kernel<<<(B + 255) / 256, 256>>>(Tinit, Tsv, out, B);
}